// round 5
// baseline (speedup 1.0000x reference)
#include <cuda_runtime.h>
#include <cstdint>

// Problem shape (fixed by the dataset):
//   features:        (BS=4, C=64, P=12000) float32
//   x_orig_indices:  (BS, P) int32  (JAX x64 disabled: "int64" is silently int32)
//   y_orig_indices:  (BS, P) int32
//   output pseudo:   (BS, C, NY=440, NX=500) float32
#define BS    4
#define CCH   64
#define NP    12000
#define NXP   500
#define NYP   440
#define CELLS (NXP * NYP)          // 220000  (divisible by 4)
#define CELLS4 (CELLS / 4)         // 55000
#define NOUT  (BS * CCH * CELLS)   // 56,320,000

// Winner array: g_winner[b][cell] = (winning p)+1, or 0 = empty.
// Zero-initialized at module load; gather_kernel re-zeroes each entry after
// reading it, so every kernel_launch call starts from a zeroed array
// (deterministic across correctness run / capture / replays).
__device__ int g_winner[BS * CELLS];

// ---------------------------------------------------------------------------
// Phase 1: winner pass — JAX sequential .set semantics == last p wins == max p.
// Store p+1 so 0 means "empty". 48000 atomicMax into L2-resident 3.5MB array.
// ---------------------------------------------------------------------------
__global__ void winner_kernel(const int* __restrict__ xi,
                              const int* __restrict__ yi) {
    int i = blockIdx.x * blockDim.x + threadIdx.x;
    if (i >= BS * NP) return;
    int b = i / NP;
    int p = i - b * NP;

    int x = xi[i];
    int y = yi[i];
    // jnp.clip semantics
    x = x < 0 ? 0 : (x >= NXP ? NXP - 1 : x);
    y = y < 0 ? 0 : (y >= NYP ? NYP - 1 : y);
    int cell = y * NXP + x;

    atomicMax(&g_winner[b * CELLS + cell], p + 1);
}

// ---------------------------------------------------------------------------
// Phase 2: fused zero-fill + gather, channels looped inside the thread.
// One thread per (b, cell4). Winner int4 read ONCE (64x less L2 traffic than
// round 4), then 64 coalesced float4 streaming stores. ~80% of threads hit
// the all-empty fast path: a pure unrolled zero-store stream.
// Each thread re-zeroes its winner entry for the next replay.
// ---------------------------------------------------------------------------
__global__ void gather_kernel(const float* __restrict__ feat,
                              float* __restrict__ out) {
    int i = blockIdx.x * blockDim.x + threadIdx.x;   // over BS*CELLS4 = 220000
    if (i >= BS * CELLS4) return;
    int b     = i / CELLS4;
    int cell4 = i - b * CELLS4;

    int4* wp = reinterpret_cast<int4*>(g_winner + b * CELLS) + cell4;
    int4 w = *wp;
    *wp = make_int4(0, 0, 0, 0);                     // reset for next launch

    float4* orow = reinterpret_cast<float4*>(out)
                 + (size_t)b * CCH * CELLS4 + cell4;

    if ((w.x | w.y | w.z | w.w) == 0) {
        // Fast path: no winners in these 4 cells -> pure write stream.
        const float4 z = make_float4(0.f, 0.f, 0.f, 0.f);
        #pragma unroll 8
        for (int c = 0; c < CCH; c++) {
            __stcs(orow, z);
            orow += CELLS4;
        }
    } else {
        const float* frow = feat + (size_t)b * CCH * NP;
        int wx = w.x - 1, wy = w.y - 1, wz = w.z - 1, ww = w.w - 1;
        #pragma unroll 4
        for (int c = 0; c < CCH; c++) {
            float4 v;
            v.x = (wx >= 0) ? __ldg(frow + wx) : 0.f;
            v.y = (wy >= 0) ? __ldg(frow + wy) : 0.f;
            v.z = (wz >= 0) ? __ldg(frow + wz) : 0.f;
            v.w = (ww >= 0) ? __ldg(frow + ww) : 0.f;
            __stcs(orow, v);
            frow += NP;
            orow += CELLS4;
        }
    }
}

// ---------------------------------------------------------------------------
extern "C" void kernel_launch(void* const* d_in, const int* in_sizes, int n_in,
                              void* d_out, int out_size) {
    const float* feat = (const float*)d_in[0];
    const int*   xi   = (const int*)d_in[1];
    const int*   yi   = (const int*)d_in[2];
    float* out = (float*)d_out;

    {   // winner pass
        int n = BS * NP;
        int threads = 256;
        int blocks = (n + threads - 1) / threads;
        winner_kernel<<<blocks, threads>>>(xi, yi);
    }
    {   // fused zero + gather (writes every output element)
        int n = BS * CELLS4;                          // 220000 threads
        int threads = 256;
        int blocks = (n + threads - 1) / threads;     // 860 blocks
        gather_kernel<<<blocks, threads>>>(feat, out);
    }
}

// round 6
// speedup vs baseline: 1.4799x; 1.4799x over previous
#include <cuda_runtime.h>
#include <cstdint>

// Problem shape (fixed by the dataset):
//   features:        (BS=4, C=64, P=12000) float32
//   x_orig_indices:  (BS, P) int32  (JAX x64 disabled: "int64" is silently int32)
//   y_orig_indices:  (BS, P) int32
//   output pseudo:   (BS, C, NY=440, NX=500) float32
#define BS     4
#define CCH    64
#define NP     12000
#define NXP    500
#define NYP    440
#define CELLS  (NXP * NYP)          // 220000  (divisible by 4)
#define CELLS4 (CELLS / 4)          // 55000
#define NOUT   (BS * CCH * CELLS)   // 56,320,000

#define CELL4_PER_BLK 64            // cell4 per block (256 cells)
#define CTILES        4             // channel tiles per block
#define C_PER_TILE    (CCH / CTILES) // 16

// Winner array: g_winner[b][cell] = (winning p)+1, or 0 = empty.
// Zero-initialized at module load; gather_kernel resets the entries it reads
// (race-free: one block owns each entry, reset after __syncthreads), so every
// kernel_launch call starts from a zeroed array.
__device__ int g_winner[BS * CELLS];

// ---------------------------------------------------------------------------
// Phase 1: winner pass — JAX sequential .set semantics == last p wins == max p.
// Store p+1 so 0 means "empty". 48000 atomicMax into L2-resident 3.5MB array.
// ---------------------------------------------------------------------------
__global__ void winner_kernel(const int* __restrict__ xi,
                              const int* __restrict__ yi) {
    int i = blockIdx.x * blockDim.x + threadIdx.x;
    if (i >= BS * NP) return;
    int b = i / NP;
    int p = i - b * NP;

    int x = xi[i];
    int y = yi[i];
    // jnp.clip semantics
    x = x < 0 ? 0 : (x >= NXP ? NXP - 1 : x);
    y = y < 0 ? 0 : (y >= NYP ? NYP - 1 : y);
    int cell = y * NXP + x;

    atomicMax(&g_winner[b * CELLS + cell], p + 1);
}

// ---------------------------------------------------------------------------
// Phase 2: fused zero-fill + gather, block-tiled (64 cell4) x (4 ctiles of 16c).
//  - warp = 32 consecutive cell4 at one channel -> every store is a contiguous
//    512B chunk; block touches only 4 planes at once -> dense DRAM streams.
//  - winner int4 read once per block (L1 broadcast across the 4 ctile warps):
//    winner L2 traffic = 3.5MB (64x less than one-thread-per-output).
//  - reset folded in race-free (single owner block, after __syncthreads).
// ---------------------------------------------------------------------------
__global__ void gather_kernel(const float* __restrict__ feat,
                              float* __restrict__ out) {
    const int b     = blockIdx.y;
    const int cell4 = blockIdx.x * CELL4_PER_BLK + (threadIdx.x & (CELL4_PER_BLK - 1));
    const int ctile = threadIdx.x >> 6;          // 0..3
    const bool active = cell4 < CELLS4;

    int4* wp = reinterpret_cast<int4*>(g_winner + b * CELLS) + cell4;
    int4 w = make_int4(0, 0, 0, 0);
    if (active) w = *wp;
    __syncthreads();
    if (active && ctile == 0) *wp = make_int4(0, 0, 0, 0);  // reset for next launch
    if (!active) return;

    const int c0 = ctile * C_PER_TILE;
    float4* orow = reinterpret_cast<float4*>(out)
                 + ((size_t)b * CCH + c0) * CELLS4 + cell4;

    if ((w.x | w.y | w.z | w.w) == 0) {
        // Fast path (~80% of cell4 groups): pure coalesced zero-store stream.
        const float4 z = make_float4(0.f, 0.f, 0.f, 0.f);
        #pragma unroll
        for (int k = 0; k < C_PER_TILE; k++) {
            __stcs(orow, z);
            orow += CELLS4;
        }
    } else {
        const float* frow = feat + ((size_t)b * CCH + c0) * NP;
        const int wx = w.x - 1, wy = w.y - 1, wz = w.z - 1, ww = w.w - 1;
        #pragma unroll 4
        for (int k = 0; k < C_PER_TILE; k++) {
            float4 v;
            v.x = (wx >= 0) ? __ldg(frow + wx) : 0.f;
            v.y = (wy >= 0) ? __ldg(frow + wy) : 0.f;
            v.z = (wz >= 0) ? __ldg(frow + wz) : 0.f;
            v.w = (ww >= 0) ? __ldg(frow + ww) : 0.f;
            __stcs(orow, v);
            frow += NP;
            orow += CELLS4;
        }
    }
}

// ---------------------------------------------------------------------------
extern "C" void kernel_launch(void* const* d_in, const int* in_sizes, int n_in,
                              void* d_out, int out_size) {
    const float* feat = (const float*)d_in[0];
    const int*   xi   = (const int*)d_in[1];
    const int*   yi   = (const int*)d_in[2];
    float* out = (float*)d_out;

    {   // winner pass
        int n = BS * NP;
        int threads = 256;
        int blocks = (n + threads - 1) / threads;
        winner_kernel<<<blocks, threads>>>(xi, yi);
    }
    {   // fused zero + gather (writes every output element, resets winner)
        dim3 grid((CELLS4 + CELL4_PER_BLK - 1) / CELL4_PER_BLK, BS);  // (860, 4)
        gather_kernel<<<grid, 256>>>(feat, out);
    }
}

// round 7
// speedup vs baseline: 2.1548x; 1.4560x over previous
#include <cuda_runtime.h>
#include <cstdint>

// Problem shape (fixed by the dataset):
//   features:        (BS=4, C=64, P=12000) float32
//   x_orig_indices:  (BS, P) int32  (JAX x64 disabled: "int64" is silently int32)
//   y_orig_indices:  (BS, P) int32
//   output pseudo:   (BS, C, NY=440, NX=500) float32
#define BS     4
#define CCH    64
#define NP     12000
#define NXP    500
#define NYP    440
#define CELLS  (NXP * NYP)          // 220000  (divisible by 8)
#define CELLS8 (CELLS / 8)          // 27500
#define NOUT   (BS * CCH * CELLS)   // 56,320,000

// Scratch (allocation-free device globals).
// g_winner: int32, (winning p)+1 or 0. Zero at module load; pack_kernel resets
//           it every launch after reading (it is the sole reader) so each
//           replay starts zeroed.
// g_w16:    uint16 compressed copy used by the gather (halves winner traffic).
__device__ int            g_winner[BS * CELLS];
__device__ unsigned short g_w16[BS * CELLS];

// ---------------------------------------------------------------------------
// Phase 1: winner pass — JAX sequential .set semantics == last p wins == max p.
// ---------------------------------------------------------------------------
__global__ void winner_kernel(const int* __restrict__ xi,
                              const int* __restrict__ yi) {
    int i = blockIdx.x * blockDim.x + threadIdx.x;
    if (i >= BS * NP) return;
    int b = i / NP;
    int p = i - b * NP;

    int x = xi[i];
    int y = yi[i];
    // jnp.clip semantics
    x = x < 0 ? 0 : (x >= NXP ? NXP - 1 : x);
    y = y < 0 ? 0 : (y >= NYP ? NYP - 1 : y);
    int cell = y * NXP + x;

    atomicMax(&g_winner[b * CELLS + cell], p + 1);
}

// ---------------------------------------------------------------------------
// Phase 2: pack int32 winner -> uint16, and reset int32 winner for the next
// launch (race-free: this kernel is the only reader of g_winner).
// 220K cells -> ~2us including launch overhead.
// ---------------------------------------------------------------------------
__global__ void pack_kernel() {
    const int n4 = (BS * CELLS) / 4;   // 220000
    int i = blockIdx.x * blockDim.x + threadIdx.x;
    if (i >= n4) return;

    int4* wp = reinterpret_cast<int4*>(g_winner) + i;
    int4 w = *wp;
    *wp = make_int4(0, 0, 0, 0);       // reset for next replay

    ushort4 s;
    s.x = (unsigned short)w.x;
    s.y = (unsigned short)w.y;
    s.z = (unsigned short)w.z;
    s.w = (unsigned short)w.w;
    reinterpret_cast<ushort4*>(g_w16)[i] = s;
}

// ---------------------------------------------------------------------------
// Phase 3: fused zero-fill + gather. ROUND-4 LAYOUT (proven best store
// pattern: each block streams one plane linearly; grid sweeps the output
// linearly). One thread per 8 cells: one 16B u16-winner load + two float4
// streaming stores. ~73% of threads take the all-empty pure-store fast path.
// ---------------------------------------------------------------------------
__global__ void gather_kernel(const float* __restrict__ feat,
                              float* __restrict__ out) {
    const int n8 = NOUT / 8;                        // 7,040,000
    int i = blockIdx.x * blockDim.x + threadIdx.x;
    if (i >= n8) return;

    int bc    = i / CELLS8;                         // b*CCH + c
    int cell8 = i - bc * CELLS8;
    int b     = bc >> 6;                            // / CCH

    // 8 cells' winners in one 16B coalesced load (L2-hot 1.75MB array).
    uint4 w = __ldg(reinterpret_cast<const uint4*>(g_w16 + b * CELLS) + cell8);

    float4* o = reinterpret_cast<float4*>(out + (size_t)bc * CELLS) + cell8 * 2;

    if ((w.x | w.y | w.z | w.w) == 0u) {
        // Fast path: pure coalesced zero-store stream.
        const float4 z = make_float4(0.f, 0.f, 0.f, 0.f);
        __stcs(o,     z);
        __stcs(o + 1, z);
    } else {
        const float* frow = feat + (size_t)bc * NP;  // 48KB row, L1/L2-hot
        int p0 = (int)(w.x & 0xFFFFu), p1 = (int)(w.x >> 16);
        int p2 = (int)(w.y & 0xFFFFu), p3 = (int)(w.y >> 16);
        int p4 = (int)(w.z & 0xFFFFu), p5 = (int)(w.z >> 16);
        int p6 = (int)(w.w & 0xFFFFu), p7 = (int)(w.w >> 16);
        float4 v0, v1;
        v0.x = p0 ? __ldg(frow + p0 - 1) : 0.f;
        v0.y = p1 ? __ldg(frow + p1 - 1) : 0.f;
        v0.z = p2 ? __ldg(frow + p2 - 1) : 0.f;
        v0.w = p3 ? __ldg(frow + p3 - 1) : 0.f;
        v1.x = p4 ? __ldg(frow + p4 - 1) : 0.f;
        v1.y = p5 ? __ldg(frow + p5 - 1) : 0.f;
        v1.z = p6 ? __ldg(frow + p6 - 1) : 0.f;
        v1.w = p7 ? __ldg(frow + p7 - 1) : 0.f;
        __stcs(o,     v0);
        __stcs(o + 1, v1);
    }
}

// ---------------------------------------------------------------------------
extern "C" void kernel_launch(void* const* d_in, const int* in_sizes, int n_in,
                              void* d_out, int out_size) {
    const float* feat = (const float*)d_in[0];
    const int*   xi   = (const int*)d_in[1];
    const int*   yi   = (const int*)d_in[2];
    float* out = (float*)d_out;

    {   // winner pass
        int n = BS * NP;
        int threads = 256;
        int blocks = (n + threads - 1) / threads;
        winner_kernel<<<blocks, threads>>>(xi, yi);
    }
    {   // pack to u16 + reset
        const int n4 = (BS * CELLS) / 4;
        int threads = 256;
        int blocks = (n4 + threads - 1) / threads;
        pack_kernel<<<blocks, threads>>>();
    }
    {   // fused zero + gather (writes every output element)
        const int n8 = NOUT / 8;
        int threads = 256;
        int blocks = (n8 + threads - 1) / threads;   // 27500 blocks
        gather_kernel<<<blocks, threads>>>(feat, out);
    }
}